// round 16
// baseline (speedup 1.0000x reference)
#include <cuda_runtime.h>
#include <math.h>

#define NN 100000
#define NE 1600000
#define EPB 384                         // edges per block (3 per thread)
#define NBLK ((NE + EPB - 1) / EPB)     // 4167; last block has no valid 3rd edge

// ---- scratch (alloc-free: __device__ globals) ----
__device__ float g_x0[NN * 5];
__device__ float g_x1[NN * 5];
__device__ float g_agg[NN * 5];
__device__ int   g_cnt[NN];
__device__ __align__(16) float g_w3t[5 * 64];   // transposed edge-w3, filled by zero_kernel

__device__ __forceinline__ float relu_(float v) { return v > 0.f ? v : 0.f; }

typedef unsigned long long u64;

__device__ __forceinline__ u64 pack2(float a, float b) {
    u64 r;
    asm("mov.b64 %0, {%1, %2};" : "=l"(r) : "f"(a), "f"(b));
    return r;
}
__device__ __forceinline__ void unpack2(u64 v, float& a, float& b) {
    asm("mov.b64 {%0, %1}, %2;" : "=f"(a), "=f"(b) : "l"(v));
}
__device__ __forceinline__ void fma2(u64& acc, u64 w, u64 a) {
    asm("fma.rn.f32x2 %0, %1, %2, %0;" : "+l"(acc) : "l"(w), "l"(a));
}
__device__ __forceinline__ void lds_v2u64(unsigned addr, u64& a, u64& b) {
    asm("ld.shared.v2.u64 {%0, %1}, [%2];" : "=l"(a), "=l"(b) : "r"(addr));
}
__device__ __forceinline__ u64 lds_u64(unsigned addr) {
    u64 r;
    asm("ld.shared.b64 %0, [%1];" : "=l"(r) : "r"(addr));
    return r;
}
__device__ __forceinline__ float lds_f32(unsigned addr) {
    float r;
    asm("ld.shared.f32 %0, [%1];" : "=f"(r) : "r"(addr));
    return r;
}
__device__ __forceinline__ void sts_f32(unsigned addr, float v) {
    asm volatile("st.shared.f32 [%0], %1;" :: "r"(addr), "f"(v));
}
__device__ __forceinline__ unsigned saddr_(const void* p) {
    return (unsigned)__cvta_generic_to_shared(p);
}

__device__ __forceinline__ void stage4(float4* dst, const float* src, int n4, int tid, int nthr) {
    const float4* s = (const float4*)src;
    for (int i = tid; i < n4; i += nthr) dst[i] = s[i];
}

// ---- single-item dense helpers (node/decoder path, unchanged from passing version)
template <int K>
__device__ __forceinline__ void dense_s(const float* hin, unsigned w_addr,
                                        unsigned bias_addr, float* hout) {
    u64 acc[32];
#pragma unroll
    for (int j = 0; j < 32; j++) acc[j] = lds_u64(bias_addr + j * 8);
#pragma unroll
    for (int k = 0; k < K; k++) {
        u64 aa = pack2(hin[k], hin[k]);
        unsigned base = w_addr + k * 256;
#pragma unroll
        for (int j = 0; j < 16; j++) {
            u64 w0, w1;
            lds_v2u64(base + j * 16, w0, w1);
            fma2(acc[2 * j], w0, aa);
            fma2(acc[2 * j + 1], w1, aa);
        }
    }
#pragma unroll
    for (int j = 0; j < 32; j++) {
        float a, b;
        unpack2(acc[j], a, b);
        hout[2 * j]     = relu_(a);
        hout[2 * j + 1] = relu_(b);
    }
}

template <int K>
__device__ __forceinline__ void dense_p(const float* hin, unsigned w_addr,
                                        unsigned bias_addr, u64* hpout) {
    u64 acc[32];
#pragma unroll
    for (int j = 0; j < 32; j++) acc[j] = lds_u64(bias_addr + j * 8);
#pragma unroll
    for (int k = 0; k < K; k++) {
        u64 aa = pack2(hin[k], hin[k]);
        unsigned base = w_addr + k * 256;
#pragma unroll
        for (int j = 0; j < 16; j++) {
            u64 w0, w1;
            lds_v2u64(base + j * 16, w0, w1);
            fma2(acc[2 * j], w0, aa);
            fma2(acc[2 * j + 1], w1, aa);
        }
    }
#pragma unroll
    for (int j = 0; j < 32; j++) {
        float a, b;
        unpack2(acc[j], a, b);
        hpout[j] = pack2(relu_(a), relu_(b));
    }
}

__device__ __forceinline__ float dot64_p(const u64* hp, unsigned w_addr, float bias) {
    u64 acc0 = 0ull, acc1 = 0ull;
#pragma unroll
    for (int j = 0; j < 16; j++) {
        u64 w0, w1;
        lds_v2u64(w_addr + j * 16, w0, w1);
        fma2(acc0, w0, hp[2 * j]);
        fma2(acc1, w1, hp[2 * j + 1]);
    }
    float a, b, c, d;
    unpack2(acc0, a, b);
    unpack2(acc1, c, d);
    return bias + ((a + b) + (c + d));
}

// ---------------------------------------------------------------- init (+ w3 transpose)
__global__ void zero_kernel(const float* __restrict__ w3) {
    int i = blockIdx.x * blockDim.x + threadIdx.x;
    if (i < NN) g_cnt[i] = 0;
    if (i < NN * 5) g_agg[i] = 0.f;
    if (i < 5 * 64) {                  // transpose [64][5] -> [5][64]
        int k = i / 5, c = i % 5;
        g_w3t[c * 64 + k] = w3[i];
    }
}

// ---------------------------------------------------------------- edge model (TRIPLE-EDGE, half-split)
// 3 edges/thread: broadcast weight LDS amortized 3x (38 wf / 96 FMA2 per k).
// 64-wide layers computed in two 32-output halves -> accs = 48 u64 (96 regs).
// All 3 edges' layer-1 activations live in per-thread smem slots [k][tid].
// Layer-3 dots streamed per half so h2 never occupies registers.
// smem: w2 16KB + 3 h slots 96KB = 112KB -> 2 CTAs/SM.
#define EDGE_SMEM_BYTES ((1024 + 3 * 2048) * 16)   // 114688

template <int ITER>
__global__ __launch_bounds__(128)
void edge_kernel(const float* __restrict__ x_in,
                 const float* __restrict__ ea,
                 const int* __restrict__ ei,
                 const float* __restrict__ w1, const float* __restrict__ b1,
                 const float* __restrict__ w2, const float* __restrict__ b2,
                 const float* __restrict__ w3t_unused, const float* __restrict__ b3) {
    extern __shared__ float4 dsm[];
    float4* s_w2 = dsm;                       // 1024 f4 = 16KB
    float*  s_h  = (float*)(dsm + 1024);      // 3 slots x 8192 floats

    int tid = threadIdx.x;
    int e0 = blockIdx.x * EPB + tid;          // always < NE (grid covers exactly)
    int e1 = e0 + 128;                        // always < NE
    int e2 = e0 + 256;
    bool has2 = (e2 < NE);                    // UNIFORM per CTA (no warp divergence)
    int e2c = has2 ? e2 : e0;

    const float* x = (ITER == 0) ? x_in : g_x0;

    // ---- gathers first (latency overlaps staging + barrier)
    int s0 = ei[e0], d0 = ei[NE + e0];
    int s1 = ei[e1], d1 = ei[NE + e1];
    int s2 = ei[e2c], d2 = ei[NE + e2c];
    const float* xs0 = x + s0 * 5; const float* xd0 = x + d0 * 5;
    const float* xs1 = x + s1 * 5; const float* xd1 = x + d1 * 5;
    const float* xs2 = x + s2 * 5; const float* xd2 = x + d2 * 5;
    float A_sx = xs0[0], A_sy = xs0[1], A_sz = xs0[2], A_sf = xs0[4];
    float A_dx = xd0[0], A_dy = xd0[1], A_dz = xd0[2], A_df = xd0[4];
    float B_sx = xs1[0], B_sy = xs1[1], B_sz = xs1[2], B_sf = xs1[4];
    float B_dx = xd1[0], B_dy = xd1[1], B_dz = xd1[2], B_df = xd1[4];
    float C_sx = xs2[0], C_sy = xs2[1], C_sz = xs2[2], C_sf = xs2[4];
    float C_dx = xd2[0], C_dy = xd2[1], C_dz = xd2[2], C_df = xd2[4];
    float EA0[5], EA1[5], EA2[5];
    {
        const float* p0 = ea + e0 * 5;
        const float* p1 = ea + e1 * 5;
        const float* p2 = ea + e2c * 5;
#pragma unroll
        for (int i = 0; i < 5; i++) { EA0[i] = p0[i]; EA1[i] = p1[i]; EA2[i] = p2[i]; }
    }

    stage4(s_w2, w2, 1024, tid, 128);
    __syncthreads();

    if (ITER == 0) {
        atomicAdd(&g_cnt[d0], 1);
        atomicAdd(&g_cnt[d1], 1);
        if (has2) atomicAdd(&g_cnt[d2], 1);
    }

    float ein0[11], ein1[11], ein2[11];
    {
        float dx = A_dx - A_sx, dy = A_dy - A_sy, dz = A_dz - A_sz;
        ein0[0] = dx; ein0[1] = dy; ein0[2] = dz;
        ein0[3] = sqrtf(fmaf(dx, dx, fmaf(dy, dy, dz * dz)));
#pragma unroll
        for (int i = 0; i < 5; i++) ein0[4 + i] = EA0[i];
        ein0[9] = A_sf; ein0[10] = A_df;
    }
    {
        float dx = B_dx - B_sx, dy = B_dy - B_sy, dz = B_dz - B_sz;
        ein1[0] = dx; ein1[1] = dy; ein1[2] = dz;
        ein1[3] = sqrtf(fmaf(dx, dx, fmaf(dy, dy, dz * dz)));
#pragma unroll
        for (int i = 0; i < 5; i++) ein1[4 + i] = EA1[i];
        ein1[9] = B_sf; ein1[10] = B_df;
    }
    {
        float dx = C_dx - C_sx, dy = C_dy - C_sy, dz = C_dz - C_sz;
        ein2[0] = dx; ein2[1] = dy; ein2[2] = dz;
        ein2[3] = sqrtf(fmaf(dx, dx, fmaf(dy, dy, dz * dz)));
#pragma unroll
        for (int i = 0; i < 5; i++) ein2[4 + i] = EA2[i];
        ein2[9] = C_sf; ein2[10] = C_df;
    }

    unsigned hA = saddr_(s_h) + tid * 4;           // [k][tid] scalar slots, conflict-free
    unsigned hB = hA + 32768;
    unsigned hC = hB + 32768;
    unsigned w2a = saddr_(s_w2);

    const ulonglong2* w1q = (const ulonglong2*)w1;  // broadcast LDG, L1-hit
    const u64* b1q = (const u64*)b1;
    const u64* b2q = (const u64*)b2;

    // ---- layer 1: 11 -> 64, two 32-output halves, 3 edges share weight loads
#pragma unroll
    for (int half = 0; half < 2; half++) {
        u64 aA[16], aB[16], aC[16];
#pragma unroll
        for (int j = 0; j < 16; j++) {
            u64 bb = __ldg(b1q + half * 16 + j);
            aA[j] = bb; aB[j] = bb; aC[j] = bb;
        }
#pragma unroll
        for (int k = 0; k < 11; k++) {
            u64 p0 = pack2(ein0[k], ein0[k]);
            u64 p1 = pack2(ein1[k], ein1[k]);
            u64 p2 = pack2(ein2[k], ein2[k]);
#pragma unroll
            for (int j = 0; j < 8; j++) {
                ulonglong2 wv = __ldg(w1q + k * 16 + half * 8 + j);
                fma2(aA[2 * j], wv.x, p0); fma2(aA[2 * j + 1], wv.y, p0);
                fma2(aB[2 * j], wv.x, p1); fma2(aB[2 * j + 1], wv.y, p1);
                fma2(aC[2 * j], wv.x, p2); fma2(aC[2 * j + 1], wv.y, p2);
            }
        }
#pragma unroll
        for (int j = 0; j < 16; j++) {
            unsigned o0 = (half * 32 + 2 * j) * 512;
            unsigned o1 = o0 + 512;
            float a, b;
            unpack2(aA[j], a, b); sts_f32(hA + o0, relu_(a)); sts_f32(hA + o1, relu_(b));
            unpack2(aB[j], a, b); sts_f32(hB + o0, relu_(a)); sts_f32(hB + o1, relu_(b));
            unpack2(aC[j], a, b); sts_f32(hC + o0, relu_(a)); sts_f32(hC + o1, relu_(b));
        }
    }
    // private [k][tid] slots: no __syncthreads needed

    // ---- layer 2 (64 -> 64) in halves; layer-3 dots streamed per half
    u64 dA[5] = {0, 0, 0, 0, 0};
    u64 dB[5] = {0, 0, 0, 0, 0};
    u64 dC[5] = {0, 0, 0, 0, 0};
    const ulonglong2* w3q = (const ulonglong2*)g_w3t;

#pragma unroll
    for (int half = 0; half < 2; half++) {
        u64 aA[16], aB[16], aC[16];
#pragma unroll
        for (int j = 0; j < 16; j++) {
            u64 bb = __ldg(b2q + half * 16 + j);
            aA[j] = bb; aB[j] = bb; aC[j] = bb;
        }
#pragma unroll 4
        for (int k = 0; k < 64; k++) {
            unsigned hoff = k * 512;
            float v0 = lds_f32(hA + hoff);
            float v1 = lds_f32(hB + hoff);
            float v2 = lds_f32(hC + hoff);
            u64 p0 = pack2(v0, v0);
            u64 p1 = pack2(v1, v1);
            u64 p2 = pack2(v2, v2);
            unsigned base2 = w2a + k * 256 + half * 128;
#pragma unroll
            for (int j = 0; j < 8; j++) {
                u64 wv0, wv1;
                lds_v2u64(base2 + j * 16, wv0, wv1);
                fma2(aA[2 * j], wv0, p0); fma2(aA[2 * j + 1], wv1, p0);
                fma2(aB[2 * j], wv0, p1); fma2(aB[2 * j + 1], wv1, p1);
                fma2(aC[2 * j], wv0, p2); fma2(aC[2 * j + 1], wv1, p2);
            }
        }
        // relu + repack in place: aX now holds packed h2 for this half
#pragma unroll
        for (int j = 0; j < 16; j++) {
            float a, b;
            unpack2(aA[j], a, b); aA[j] = pack2(relu_(a), relu_(b));
            unpack2(aB[j], a, b); aB[j] = pack2(relu_(a), relu_(b));
            unpack2(aC[j], a, b); aC[j] = pack2(relu_(a), relu_(b));
        }
        // streamed layer-3 partial dots over this half (w3t broadcast LDG, L1-hit)
#pragma unroll
        for (int c = 0; c < 5; c++) {
#pragma unroll
            for (int j = 0; j < 8; j++) {
                ulonglong2 wv = __ldg(w3q + c * 16 + half * 8 + j);
                fma2(dA[c], wv.x, aA[2 * j]); fma2(dA[c], wv.y, aA[2 * j + 1]);
                fma2(dB[c], wv.x, aB[2 * j]); fma2(dB[c], wv.y, aB[2 * j + 1]);
                fma2(dC[c], wv.x, aC[2 * j]); fma2(dC[c], wv.y, aC[2 * j + 1]);
            }
        }
    }

    // ---- finalize: residual + bias, scatter
    float* ap0 = g_agg + d0 * 5;
    float* ap1 = g_agg + d1 * 5;
    float* ap2 = g_agg + d2 * 5;
#pragma unroll
    for (int c = 0; c < 5; c++) {
        float bc = __ldg(b3 + c);
        float a, b;
        unpack2(dA[c], a, b);
        atomicAdd(ap0 + c, EA0[c] + bc + (a + b));
        unpack2(dB[c], a, b);
        atomicAdd(ap1 + c, EA1[c] + bc + (a + b));
        if (has2) {
            unpack2(dC[c], a, b);
            atomicAdd(ap2 + c, EA2[c] + bc + (a + b));
        }
    }
}

// ---------------------------------------------------------------- node model (unchanged)
template <int ITER>
__global__ __launch_bounds__(128)
void node_kernel(const float* __restrict__ x_in,
                 const float* __restrict__ w1, const float* __restrict__ b1,
                 const float* __restrict__ w2, const float* __restrict__ b2,
                 const float* __restrict__ w3, const float* __restrict__ b3) {
    __shared__ float4 s_w1[7 * 16];
    __shared__ float4 s_w2[64 * 16];
    __shared__ float4 s_w3[16];
    __shared__ __align__(16) float s_b1[64];
    __shared__ __align__(16) float s_b2[64];
    __shared__ float s_b3;

    int n = blockIdx.x * blockDim.x + threadIdx.x;
    bool active = (n < NN);
    int n_c = active ? n : 0;

    const float* x = (ITER == 0) ? x_in : g_x0;
    float xc0 = x[n_c * 5 + 0], xc1 = x[n_c * 5 + 1], xc2 = x[n_c * 5 + 2],
          xc3 = x[n_c * 5 + 3], xc4 = x[n_c * 5 + 4];
    int c = g_cnt[n_c];
    float a0 = g_agg[n_c * 5 + 0], a1 = g_agg[n_c * 5 + 1], a2 = g_agg[n_c * 5 + 2],
          a3 = g_agg[n_c * 5 + 3], a4 = g_agg[n_c * 5 + 4];

    {
        int tid = threadIdx.x;
        stage4(s_w1, w1, 7 * 16, tid, blockDim.x);
        stage4(s_w2, w2, 64 * 16, tid, blockDim.x);
        stage4(s_w3, w3, 16, tid, blockDim.x);
        stage4((float4*)s_b1, b1, 16, tid, blockDim.x);
        stage4((float4*)s_b2, b2, 16, tid, blockDim.x);
        if (tid == 0) s_b3 = b3[0];
    }
    __syncthreads();

    if (!active) return;

    g_agg[n * 5 + 0] = 0.f;
    g_agg[n * 5 + 1] = 0.f;
    g_agg[n * 5 + 2] = 0.f;
    g_agg[n * 5 + 3] = 0.f;
    g_agg[n * 5 + 4] = 0.f;

    float inv = 1.0f / (float)(c > 0 ? c : 1);
    float nin[7];
    nin[0] = xc3;
    nin[1] = xc4;
    nin[2] = a0 * inv;
    nin[3] = a1 * inv;
    nin[4] = a2 * inv;
    nin[5] = a3 * inv;
    nin[6] = a4 * inv;

    float h[64];
    dense_s<7>(nin, saddr_(s_w1), saddr_(s_b1), h);
    u64 hp[32];
    dense_p<64>(h, saddr_(s_w2), saddr_(s_b2), hp);

    float dphi = dot64_p(hp, saddr_(s_w3), s_b3);

    float v0 = xc0, v1 = xc1, v2 = xc2, v3 = xc3, v4 = xc4 + dphi;
    float* xo = (ITER == 0) ? g_x0 : g_x1;
    xo[n * 5 + 0] = v0 + relu_(v0);
    xo[n * 5 + 1] = v1 + relu_(v1);
    xo[n * 5 + 2] = v2 + relu_(v2);
    xo[n * 5 + 3] = v3 + relu_(v3);
    xo[n * 5 + 4] = v4 + relu_(v4);
}

// ---------------------------------------------------------------- decoder (unchanged)
__global__ __launch_bounds__(128)
void decoder_kernel(const float* __restrict__ w1, const float* __restrict__ b1,
                    const float* __restrict__ w2, const float* __restrict__ b2,
                    const float* __restrict__ w3, const float* __restrict__ b3,
                    const float* __restrict__ w4, const float* __restrict__ b4,
                    float* __restrict__ out) {
    __shared__ float4 s_w1[5 * 16];
    __shared__ float4 s_w2[64 * 16];
    __shared__ float4 s_w3[64 * 16];
    __shared__ float4 s_w4[16];
    __shared__ __align__(16) float s_b1[64];
    __shared__ __align__(16) float s_b2[64];
    __shared__ __align__(16) float s_b3[64];
    __shared__ float s_b4;

    int n = blockIdx.x * blockDim.x + threadIdx.x;
    bool active = (n < NN);
    int n_c = active ? n : 0;
    float xin[5];
#pragma unroll
    for (int i = 0; i < 5; i++) xin[i] = g_x1[n_c * 5 + i];

    {
        int tid = threadIdx.x;
        stage4(s_w1, w1, 5 * 16, tid, blockDim.x);
        stage4(s_w2, w2, 64 * 16, tid, blockDim.x);
        stage4(s_w3, w3, 64 * 16, tid, blockDim.x);
        stage4(s_w4, w4, 16, tid, blockDim.x);
        stage4((float4*)s_b1, b1, 16, tid, blockDim.x);
        stage4((float4*)s_b2, b2, 16, tid, blockDim.x);
        stage4((float4*)s_b3, b3, 16, tid, blockDim.x);
        if (tid == 0) s_b4 = b4[0];
    }
    __syncthreads();

    if (!active) return;

    float h[64];
    dense_s<5>(xin, saddr_(s_w1), saddr_(s_b1), h);
    dense_s<64>(h,  saddr_(s_w2), saddr_(s_b2), h);
    u64 hp[32];
    dense_p<64>(h,  saddr_(s_w3), saddr_(s_b3), hp);

    out[n] = dot64_p(hp, saddr_(s_w4), s_b4);
}

// ---------------------------------------------------------------- launch
extern "C" void kernel_launch(void* const* d_in, const int* in_sizes, int n_in,
                              void* d_out, int out_size) {
    const float* x   = (const float*)d_in[0];
    const float* ea  = (const float*)d_in[1];
    const float* ew1 = (const float*)d_in[2];
    const float* eb1 = (const float*)d_in[3];
    const float* ew2 = (const float*)d_in[4];
    const float* eb2 = (const float*)d_in[5];
    const float* ew3 = (const float*)d_in[6];
    const float* eb3 = (const float*)d_in[7];
    const float* nw1 = (const float*)d_in[8];
    const float* nb1 = (const float*)d_in[9];
    const float* nw2 = (const float*)d_in[10];
    const float* nb2 = (const float*)d_in[11];
    const float* nw3 = (const float*)d_in[12];
    const float* nb3 = (const float*)d_in[13];
    const float* dw1 = (const float*)d_in[14];
    const float* db1 = (const float*)d_in[15];
    const float* dw2 = (const float*)d_in[16];
    const float* db2 = (const float*)d_in[17];
    const float* dw3 = (const float*)d_in[18];
    const float* db3 = (const float*)d_in[19];
    const float* dw4 = (const float*)d_in[20];
    const float* db4 = (const float*)d_in[21];
    const int*   ei  = (const int*)d_in[22];
    float* out = (float*)d_out;

    cudaFuncSetAttribute(edge_kernel<0>, cudaFuncAttributeMaxDynamicSharedMemorySize, EDGE_SMEM_BYTES);
    cudaFuncSetAttribute(edge_kernel<1>, cudaFuncAttributeMaxDynamicSharedMemorySize, EDGE_SMEM_BYTES);

    zero_kernel<<<(NN * 5 + 255) / 256, 256>>>(ew3);

    edge_kernel<0><<<NBLK, 128, EDGE_SMEM_BYTES>>>(x, ea, ei, ew1, eb1, ew2, eb2, ew3, eb3);
    node_kernel<0><<<(NN + 127) / 128, 128>>>(x, nw1, nb1, nw2, nb2, nw3, nb3);

    edge_kernel<1><<<NBLK, 128, EDGE_SMEM_BYTES>>>(x, ea, ei, ew1, eb1, ew2, eb2, ew3, eb3);
    node_kernel<1><<<(NN + 127) / 128, 128>>>(x, nw1, nb1, nw2, nb2, nw3, nb3);

    decoder_kernel<<<(NN + 127) / 128, 128>>>(dw1, db1, dw2, db2, dw3, db3, dw4, db4, out);
}